// round 8
// baseline (speedup 1.0000x reference)
#include <cuda_runtime.h>
#include <math.h>

#define DT   1e-3f
#define INVH 0.1f

__device__ __forceinline__ float4 ldf4(const float* p) {
    return *reinterpret_cast<const float4*>(p);
}

// Fused single kernel: each thread owns a 4-wide x-quad at row z, loops over
// batches. Velocities at rows z-1/z/z+1 recomputed in registers from stresses.
__global__ __launch_bounds__(256, 4)
void fused_kernel(const float* __restrict__ vp,  const float* __restrict__ vs,
                  const float* __restrict__ rho,
                  const float* __restrict__ vx,  const float* __restrict__ vz,
                  const float* __restrict__ txx, const float* __restrict__ tzz,
                  const float* __restrict__ txz, const float* __restrict__ dmp,
                  float* __restrict__ out, int B, int NZ, int NX)
{
    const int x4 = (blockIdx.x * 32 + threadIdx.x) * 4;
    const int z  = blockIdx.y * 8 + threadIdx.y;
    if (x4 >= NX || z >= NZ) return;
    const int plane = NZ * NX;

    const int r0 = z * NX;
    const int rm = ((z == 0) ? NZ - 1 : z - 1) * NX;
    const int rp = ((z == NZ - 1) ? 0 : z + 1) * NX;
    const int xm  = (x4 == 0)      ? NX - 1 : x4 - 1;
    const int xp4 = (x4 + 4 == NX) ? 0      : x4 + 4;

    // ---------------- coefficients (batch-invariant) ----------------
    const float4 d0 = ldf4(dmp + r0 + x4);
    const float4 dM = ldf4(dmp + rm + x4);
    const float4 dP = ldf4(dmp + rp + x4);
    const float  d0m = dmp[r0 + xm], d0p = dmp[r0 + xp4];
    const float4 q0 = ldf4(rho + r0 + x4);
    const float4 qM = ldf4(rho + rm + x4);
    const float4 qP = ldf4(rho + rp + x4);
    const float  q0m = rho[r0 + xm], q0p = rho[r0 + xp4];

    float a0[4], br0[4], aM[4], brM[4], aP[4], brP[4], bco[4];
    float a0m, br0m, a0p, br0p;
    {
        const float dd0[4] = {d0.x, d0.y, d0.z, d0.w};
        const float ddM[4] = {dM.x, dM.y, dM.z, dM.w};
        const float ddP[4] = {dP.x, dP.y, dP.z, dP.w};
        const float qq0[4] = {q0.x, q0.y, q0.z, q0.w};
        const float qqM[4] = {qM.x, qM.y, qM.z, qM.w};
        const float qqP[4] = {qP.x, qP.y, qP.z, qP.w};
        #pragma unroll
        for (int i = 0; i < 4; i++) {
            float c, inv;
            c = 0.5f * DT * dd0[i]; inv = __fdividef(1.0f, 1.0f + c);
            a0[i] = (1.0f - c) * inv; bco[i] = DT * inv;
            br0[i] = __fdividef(DT * inv * INVH, qq0[i]);
            c = 0.5f * DT * ddM[i]; inv = __fdividef(1.0f, 1.0f + c);
            aM[i] = (1.0f - c) * inv;
            brM[i] = __fdividef(DT * inv * INVH, qqM[i]);
            c = 0.5f * DT * ddP[i]; inv = __fdividef(1.0f, 1.0f + c);
            aP[i] = (1.0f - c) * inv;
            brP[i] = __fdividef(DT * inv * INVH, qqP[i]);
        }
        float c, inv;
        c = 0.5f * DT * d0m; inv = __fdividef(1.0f, 1.0f + c);
        a0m = (1.0f - c) * inv; br0m = __fdividef(DT * inv * INVH, q0m);
        c = 0.5f * DT * d0p; inv = __fdividef(1.0f, 1.0f + c);
        a0p = (1.0f - c) * inv; br0p = __fdividef(DT * inv * INVH, q0p);
    }
    float mu[4], lam[4], lp2m[4];
    {
        const float4 s4 = ldf4(vs + r0 + x4);
        const float4 p4 = ldf4(vp + r0 + x4);
        const float ss[4] = {s4.x, s4.y, s4.z, s4.w};
        const float pp[4] = {p4.x, p4.y, p4.z, p4.w};
        const float qq[4] = {q0.x, q0.y, q0.z, q0.w};
        #pragma unroll
        for (int i = 0; i < 4; i++) {
            mu[i]   = qq[i] * ss[i] * ss[i];
            lam[i]  = qq[i] * pp[i] * pp[i] - 2.0f * mu[i];
            lp2m[i] = lam[i] + 2.0f * mu[i];
        }
    }

    const int bplane = B * plane;
    const int gq = r0 + x4;   // quad base within a plane

    #pragma unroll 1
    for (int b = 0; b < B; b++) {
        const int o = b * plane;

        // ---- loads ----
        const float4 txx0 = ldf4(txx + o + gq);
        const float  txx0m = txx[o + r0 + xm];
        const float  txx0p = txx[o + r0 + xp4];
        const float4 txxP = ldf4(txx + o + rp + x4);
        const float  txxPm = txx[o + rp + xm];

        const float4 txz0 = ldf4(txz + o + gq);
        const float  txz0m = txz[o + r0 + xm];
        const float  txz0p = txz[o + r0 + xp4];
        const float4 txzM = ldf4(txz + o + rm + x4);
        const float  txzMp = txz[o + rm + xp4];
        const float4 txzP = ldf4(txz + o + rp + x4);

        const float4 tzz0 = ldf4(tzz + o + gq);
        const float  tzz0m = tzz[o + r0 + xm];
        const float4 tzzP = ldf4(tzz + o + rp + x4);
        const float  tzzPm = tzz[o + rp + xm];
        const float4 tzzM = ldf4(tzz + o + rm + x4);

        const float4 vx0 = ldf4(vx + o + gq);
        const float  vx0p = vx[o + r0 + xp4];
        const float4 vxP = ldf4(vx + o + rp + x4);
        const float4 vz0 = ldf4(vz + o + gq);
        const float  vz0m = vz[o + r0 + xm];
        const float4 vzM = ldf4(vz + o + rm + x4);

        const float txxr0[6] = {txx0m, txx0.x, txx0.y, txx0.z, txx0.w, txx0p};
        const float txzr0[6] = {txz0m, txz0.x, txz0.y, txz0.z, txz0.w, txz0p};
        const float txzrm[5] = {txzM.x, txzM.y, txzM.z, txzM.w, txzMp};
        const float tzzr0[5] = {tzz0m, tzz0.x, tzz0.y, tzz0.z, tzz0.w};
        const float tzzrp[5] = {tzzPm, tzzP.x, tzzP.y, tzzP.z, tzzP.w};

        // ---- velocity recompute (tight scopes to limit live ranges) ----
        float vxnA[5];
        {
            const float vxr0[5] = {vx0.x, vx0.y, vx0.z, vx0.w, vx0p};
            const float av0[5]  = {a0[0], a0[1], a0[2], a0[3], a0p};
            const float brv0[5] = {br0[0], br0[1], br0[2], br0[3], br0p};
            #pragma unroll
            for (int i = 0; i < 5; i++)
                vxnA[i] = av0[i] * vxr0[i]
                        + brv0[i] * ((txxr0[i + 1] - txxr0[i]) + (txzr0[i + 1] - txzrm[i]));
        }
        float vxnB[4];
        {
            const float txxrp[5] = {txxPm, txxP.x, txxP.y, txxP.z, txxP.w};
            const float vxrp[4]  = {vxP.x, vxP.y, vxP.z, vxP.w};
            const float txzp_[4] = {txzP.x, txzP.y, txzP.z, txzP.w};
            #pragma unroll
            for (int i = 0; i < 4; i++)
                vxnB[i] = aP[i] * vxrp[i]
                        + brP[i] * ((txxrp[i + 1] - txxrp[i]) + (txzp_[i] - txzr0[i + 1]));
        }
        float vznA[5];
        {
            const float vzr0[5]  = {vz0m, vz0.x, vz0.y, vz0.z, vz0.w};
            const float av0m[5]  = {a0m, a0[0], a0[1], a0[2], a0[3]};
            const float brv0m[5] = {br0m, br0[0], br0[1], br0[2], br0[3]};
            #pragma unroll
            for (int j = 0; j < 5; j++)
                vznA[j] = av0m[j] * vzr0[j]
                        + brv0m[j] * ((txzr0[j + 1] - txzr0[j]) + (tzzrp[j] - tzzr0[j]));
        }
        float vznB[4];
        {
            const float vzrm[4]  = {vzM.x, vzM.y, vzM.z, vzM.w};
            const float tzzm_[4] = {tzzM.x, tzzM.y, tzzM.z, tzzM.w};
            const float tzz0_[4] = {tzz0.x, tzz0.y, tzz0.z, tzz0.w};
            #pragma unroll
            for (int i = 0; i < 4; i++)
                vznB[i] = aM[i] * vzrm[i]
                        + brM[i] * ((txzrm[i + 1] - txzrm[i]) + (tzz0_[i] - tzzm_[i]));
        }

        // ---- stress update + writes ----
        const float txx0_[4] = {txx0.x, txx0.y, txx0.z, txx0.w};
        const float tzz0_[4] = {tzz0.x, tzz0.y, tzz0.z, tzz0.w};
        const float txz0_[4] = {txz0.x, txz0.y, txz0.z, txz0.w};
        float4 vxn4, vzn4, txxn4, tzzn4, txzn4;
        float* pvx = &vxn4.x;  float* pvz = &vzn4.x;
        float* pxx = &txxn4.x; float* pzz = &tzzn4.x; float* pxz = &txzn4.x;
        #pragma unroll
        for (int i = 0; i < 4; i++) {
            const float vx_x  = (vxnA[i + 1] - vxnA[i]) * INVH;
            const float vz_z  = (vznA[i + 1] - vznB[i]) * INVH;
            const float vx_zp = (vxnB[i] - vxnA[i]) * INVH;
            const float vz_xm = (vznA[i + 1] - vznA[i]) * INVH;
            pvx[i] = vxnA[i];
            pvz[i] = vznA[i + 1];
            pxx[i] = a0[i] * txx0_[i] + bco[i] * (lp2m[i] * vx_x + lam[i] * vz_z);
            pzz[i] = a0[i] * tzz0_[i] + bco[i] * (lp2m[i] * vz_z + lam[i] * vx_x);
            pxz[i] = a0[i] * txz0_[i] + bco[i] * (mu[i] * (vx_zp + vz_xm));
        }
        float* wbase = out + o + gq;
        __stcs(reinterpret_cast<float4*>(wbase), vxn4);
        __stcs(reinterpret_cast<float4*>(wbase + bplane), vzn4);
        __stcs(reinterpret_cast<float4*>(wbase + 2 * bplane), txxn4);
        __stcs(reinterpret_cast<float4*>(wbase + 3 * bplane), tzzn4);
        __stcs(reinterpret_cast<float4*>(wbase + 4 * bplane), txzn4);
    }
}

extern "C" void kernel_launch(void* const* d_in, const int* in_sizes, int n_in,
                              void* d_out, int out_size) {
    const float* vp  = (const float*)d_in[0];
    const float* vs  = (const float*)d_in[1];
    const float* rho = (const float*)d_in[2];
    const float* vx  = (const float*)d_in[3];
    const float* vz  = (const float*)d_in[4];
    const float* txx = (const float*)d_in[5];
    const float* tzz = (const float*)d_in[6];
    const float* txz = (const float*)d_in[7];
    const float* dmp = (const float*)d_in[8];
    float* out = (float*)d_out;

    int plane = in_sizes[0];             // NZ * NX
    int B = in_sizes[3] / plane;         // batch from vx size
    int NX = 1;
    while (NX * NX < plane) NX <<= 1;    // square power-of-two grid (2048)
    int NZ = plane / NX;

    dim3 block(32, 8);
    dim3 grid((NX / 4 + 31) / 32, (NZ + 7) / 8);
    fused_kernel<<<grid, block>>>(vp, vs, rho, vx, vz, txx, tzz, txz, dmp,
                                  out, B, NZ, NX);
}

// round 9
// speedup vs baseline: 1.0773x; 1.0773x over previous
#include <cuda_runtime.h>
#include <math.h>

#define DT   1e-3f
#define INVH 0.1f

__device__ __forceinline__ float4 ldf4(const float* p) {
    return *reinterpret_cast<const float4*>(p);
}

// Fused single kernel, one batch per blockIdx.z. Each thread owns a 4-wide
// x-quad at row z. Velocities at rows z-1/z/z+1 recomputed in registers from
// stresses (no smem, no barriers). Coefficient maps are L2-resident.
__global__ __launch_bounds__(256, 3)
void fused_kernel(const float* __restrict__ vp,  const float* __restrict__ vs,
                  const float* __restrict__ rho,
                  const float* __restrict__ vx,  const float* __restrict__ vz,
                  const float* __restrict__ txx, const float* __restrict__ tzz,
                  const float* __restrict__ txz, const float* __restrict__ dmp,
                  float* __restrict__ out, int B, int NZ, int NX)
{
    const int x4 = (blockIdx.x * 32 + threadIdx.x) * 4;
    const int z  = blockIdx.y * 8 + threadIdx.y;
    if (x4 >= NX || z >= NZ) return;
    const int plane = NZ * NX;
    const int o = blockIdx.z * plane;

    const int r0 = z * NX;
    const int rm = ((z == 0) ? NZ - 1 : z - 1) * NX;
    const int rp = ((z == NZ - 1) ? 0 : z + 1) * NX;
    const int xm  = (x4 == 0)      ? NX - 1 : x4 - 1;
    const int xp4 = (x4 + 4 == NX) ? 0      : x4 + 4;
    const int gq = r0 + x4;

    // ---- field loads (burst for MLP) ----
    const float4 txx0 = ldf4(txx + o + gq);
    const float  txx0m = txx[o + r0 + xm];
    const float  txx0p = txx[o + r0 + xp4];
    const float4 txxP = ldf4(txx + o + rp + x4);
    const float  txxPm = txx[o + rp + xm];

    const float4 txz0 = ldf4(txz + o + gq);
    const float  txz0m = txz[o + r0 + xm];
    const float  txz0p = txz[o + r0 + xp4];
    const float4 txzM = ldf4(txz + o + rm + x4);
    const float  txzMp = txz[o + rm + xp4];
    const float4 txzP = ldf4(txz + o + rp + x4);

    const float4 tzz0 = ldf4(tzz + o + gq);
    const float  tzz0m = tzz[o + r0 + xm];
    const float4 tzzP = ldf4(tzz + o + rp + x4);
    const float  tzzPm = tzz[o + rp + xm];
    const float4 tzzM = ldf4(tzz + o + rm + x4);

    const float4 vx0 = ldf4(vx + o + gq);
    const float  vx0p = vx[o + r0 + xp4];
    const float4 vxP = ldf4(vx + o + rp + x4);
    const float4 vz0 = ldf4(vz + o + gq);
    const float  vz0m = vz[o + r0 + xm];
    const float4 vzM = ldf4(vz + o + rm + x4);

    const float txxr0[6] = {txx0m, txx0.x, txx0.y, txx0.z, txx0.w, txx0p};
    const float txzr0[6] = {txz0m, txz0.x, txz0.y, txz0.z, txz0.w, txz0p};
    const float txzrm[5] = {txzM.x, txzM.y, txzM.z, txzM.w, txzMp};
    const float tzzr0[5] = {tzz0m, tzz0.x, tzz0.y, tzz0.z, tzz0.w};
    const float tzzrp[5] = {tzzPm, tzzP.x, tzzP.y, tzzP.z, tzzP.w};

    // ---- row-z coefficients (a, bco for stress; a/br extended over x) ----
    float a0[4], bco[4];
    float vxnA[5];
    {
        const float4 d0 = ldf4(dmp + gq);
        const float4 q0r = ldf4(rho + gq);
        const float  d0p = dmp[r0 + xp4];
        const float  q0p = rho[r0 + xp4];
        const float dd[5] = {d0.x, d0.y, d0.z, d0.w, d0p};
        const float qq[5] = {q0r.x, q0r.y, q0r.z, q0r.w, q0p};
        const float vxr0[5] = {vx0.x, vx0.y, vx0.z, vx0.w, vx0p};
        #pragma unroll
        for (int i = 0; i < 5; i++) {
            const float c   = 0.5f * DT * dd[i];
            const float inv = __fdividef(1.0f, 1.0f + c);
            const float a   = (1.0f - c) * inv;
            const float br  = __fdividef(DT * inv * INVH, qq[i]);
            if (i < 4) { a0[i] = a; bco[i] = DT * inv; }
            vxnA[i] = a * vxr0[i]
                    + br * ((txxr0[i + 1] - txxr0[i]) + (txzr0[i + 1] - txzrm[i]));
        }
    }
    // vznA: row z, x4-1..x4+3 (needs a/br at those x)
    float vznA[5];
    {
        const float  d0m = dmp[r0 + xm];
        const float  q0m = rho[r0 + xm];
        const float4 d0 = ldf4(dmp + gq);
        const float4 q0r = ldf4(rho + gq);
        const float dd[5] = {d0m, d0.x, d0.y, d0.z, d0.w};
        const float qq[5] = {q0m, q0r.x, q0r.y, q0r.z, q0r.w};
        const float vzr0[5] = {vz0m, vz0.x, vz0.y, vz0.z, vz0.w};
        #pragma unroll
        for (int j = 0; j < 5; j++) {
            const float c   = 0.5f * DT * dd[j];
            const float inv = __fdividef(1.0f, 1.0f + c);
            const float a   = (1.0f - c) * inv;
            const float br  = __fdividef(DT * inv * INVH, qq[j]);
            vznA[j] = a * vzr0[j]
                    + br * ((txzr0[j + 1] - txzr0[j]) + (tzzrp[j] - tzzr0[j]));
        }
    }
    // vxnB: row z+1, x4..x4+3
    float vxnB[4];
    {
        const float4 dP = ldf4(dmp + rp + x4);
        const float4 qP = ldf4(rho + rp + x4);
        const float ddP[4] = {dP.x, dP.y, dP.z, dP.w};
        const float qqP[4] = {qP.x, qP.y, qP.z, qP.w};
        const float txxrp[5] = {txxPm, txxP.x, txxP.y, txxP.z, txxP.w};
        const float vxrp[4]  = {vxP.x, vxP.y, vxP.z, vxP.w};
        const float txzp_[4] = {txzP.x, txzP.y, txzP.z, txzP.w};
        #pragma unroll
        for (int i = 0; i < 4; i++) {
            const float c   = 0.5f * DT * ddP[i];
            const float inv = __fdividef(1.0f, 1.0f + c);
            const float a   = (1.0f - c) * inv;
            const float br  = __fdividef(DT * inv * INVH, qqP[i]);
            vxnB[i] = a * vxrp[i]
                    + br * ((txxrp[i + 1] - txxrp[i]) + (txzp_[i] - txzr0[i + 1]));
        }
    }
    // vznB: row z-1, x4..x4+3
    float vznB[4];
    {
        const float4 dM = ldf4(dmp + rm + x4);
        const float4 qM = ldf4(rho + rm + x4);
        const float ddM[4] = {dM.x, dM.y, dM.z, dM.w};
        const float qqM[4] = {qM.x, qM.y, qM.z, qM.w};
        const float vzrm[4]  = {vzM.x, vzM.y, vzM.z, vzM.w};
        const float tzzm_[4] = {tzzM.x, tzzM.y, tzzM.z, tzzM.w};
        const float tzz0_[4] = {tzz0.x, tzz0.y, tzz0.z, tzz0.w};
        #pragma unroll
        for (int i = 0; i < 4; i++) {
            const float c   = 0.5f * DT * ddM[i];
            const float inv = __fdividef(1.0f, 1.0f + c);
            const float a   = (1.0f - c) * inv;
            const float br  = __fdividef(DT * inv * INVH, qqM[i]);
            vznB[i] = a * vzrm[i]
                    + br * ((txzrm[i + 1] - txzrm[i]) + (tzz0_[i] - tzzm_[i]));
        }
    }

    // ---- stress material coeffs + update + writes ----
    const float txx0_[4] = {txx0.x, txx0.y, txx0.z, txx0.w};
    const float tzz0_[4] = {tzz0.x, tzz0.y, tzz0.z, tzz0.w};
    const float txz0_[4] = {txz0.x, txz0.y, txz0.z, txz0.w};
    float4 vxn4, vzn4, txxn4, tzzn4, txzn4;
    float* pvx = &vxn4.x;  float* pvz = &vzn4.x;
    float* pxx = &txxn4.x; float* pzz = &tzzn4.x; float* pxz = &txzn4.x;
    {
        const float4 s4 = ldf4(vs + gq);
        const float4 p4 = ldf4(vp + gq);
        const float4 q0r = ldf4(rho + gq);
        const float ss[4] = {s4.x, s4.y, s4.z, s4.w};
        const float pp[4] = {p4.x, p4.y, p4.z, p4.w};
        const float qq[4] = {q0r.x, q0r.y, q0r.z, q0r.w};
        #pragma unroll
        for (int i = 0; i < 4; i++) {
            const float mu   = qq[i] * ss[i] * ss[i];
            const float lam  = qq[i] * pp[i] * pp[i] - 2.0f * mu;
            const float lp2m = lam + 2.0f * mu;
            const float vx_x  = (vxnA[i + 1] - vxnA[i]) * INVH;
            const float vz_z  = (vznA[i + 1] - vznB[i]) * INVH;
            const float vx_zp = (vxnB[i] - vxnA[i]) * INVH;
            const float vz_xm = (vznA[i + 1] - vznA[i]) * INVH;
            pvx[i] = vxnA[i];
            pvz[i] = vznA[i + 1];
            pxx[i] = a0[i] * txx0_[i] + bco[i] * (lp2m * vx_x + lam * vz_z);
            pzz[i] = a0[i] * tzz0_[i] + bco[i] * (lp2m * vz_z + lam * vx_x);
            pxz[i] = a0[i] * txz0_[i] + bco[i] * (mu * (vx_zp + vz_xm));
        }
    }
    const int bplane = B * plane;
    float* wbase = out + o + gq;
    __stcs(reinterpret_cast<float4*>(wbase), vxn4);
    __stcs(reinterpret_cast<float4*>(wbase + bplane), vzn4);
    __stcs(reinterpret_cast<float4*>(wbase + 2 * bplane), txxn4);
    __stcs(reinterpret_cast<float4*>(wbase + 3 * bplane), tzzn4);
    __stcs(reinterpret_cast<float4*>(wbase + 4 * bplane), txzn4);
}

extern "C" void kernel_launch(void* const* d_in, const int* in_sizes, int n_in,
                              void* d_out, int out_size) {
    const float* vp  = (const float*)d_in[0];
    const float* vs  = (const float*)d_in[1];
    const float* rho = (const float*)d_in[2];
    const float* vx  = (const float*)d_in[3];
    const float* vz  = (const float*)d_in[4];
    const float* txx = (const float*)d_in[5];
    const float* tzz = (const float*)d_in[6];
    const float* txz = (const float*)d_in[7];
    const float* dmp = (const float*)d_in[8];
    float* out = (float*)d_out;

    int plane = in_sizes[0];             // NZ * NX
    int B = in_sizes[3] / plane;         // batch from vx size
    int NX = 1;
    while (NX * NX < plane) NX <<= 1;    // square power-of-two grid (2048)
    int NZ = plane / NX;

    dim3 block(32, 8);
    dim3 grid((NX / 4 + 31) / 32, (NZ + 7) / 8, B);
    fused_kernel<<<grid, block>>>(vp, vs, rho, vx, vz, txx, tzz, txz, dmp,
                                  out, B, NZ, NX);
}

// round 10
// speedup vs baseline: 1.1390x; 1.0573x over previous
#include <cuda_runtime.h>
#include <math.h>

#define DT   1e-3f
#define INVH 0.1f

__device__ __forceinline__ float4 ldf4(const float* p) {
    return *reinterpret_cast<const float4*>(p);
}

// Fused kernel: thread owns a 4-wide x-quad at row z, loops over batches.
// Velocities at rows z-1/z/z+1 recomputed in registers from stresses.
// Coefficients recomputed INSIDE the batch loop from map loads that are
// L1-resident after the first iteration (same thread, same addresses).
__global__ __launch_bounds__(256, 3)
void fused_kernel(const float* __restrict__ vp,  const float* __restrict__ vs,
                  const float* __restrict__ rho,
                  const float* __restrict__ vx,  const float* __restrict__ vz,
                  const float* __restrict__ txx, const float* __restrict__ tzz,
                  const float* __restrict__ txz, const float* __restrict__ dmp,
                  float* __restrict__ out, int B, int NZ, int NX)
{
    const int x4 = (blockIdx.x * 32 + threadIdx.x) * 4;
    const int z  = blockIdx.y * 8 + threadIdx.y;
    if (x4 >= NX || z >= NZ) return;
    const int plane = NZ * NX;

    const int r0 = z * NX;
    const int rm = ((z == 0) ? NZ - 1 : z - 1) * NX;
    const int rp = ((z == NZ - 1) ? 0 : z + 1) * NX;
    const int xm  = (x4 == 0)      ? NX - 1 : x4 - 1;
    const int xp4 = (x4 + 4 == NX) ? 0      : x4 + 4;
    const int gq = r0 + x4;
    const int bplane = B * plane;

    #pragma unroll 1
    for (int b = 0; b < B; b++) {
        const int o = b * plane;

        // ---- field loads (burst for MLP) ----
        const float4 txx0 = ldf4(txx + o + gq);
        const float  txx0m = txx[o + r0 + xm];
        const float  txx0p = txx[o + r0 + xp4];
        const float4 txxP = ldf4(txx + o + rp + x4);
        const float  txxPm = txx[o + rp + xm];

        const float4 txz0 = ldf4(txz + o + gq);
        const float  txz0m = txz[o + r0 + xm];
        const float  txz0p = txz[o + r0 + xp4];
        const float4 txzM = ldf4(txz + o + rm + x4);
        const float  txzMp = txz[o + rm + xp4];
        const float4 txzP = ldf4(txz + o + rp + x4);

        const float4 tzz0 = ldf4(tzz + o + gq);
        const float  tzz0m = tzz[o + r0 + xm];
        const float4 tzzP = ldf4(tzz + o + rp + x4);
        const float  tzzPm = tzz[o + rp + xm];
        const float4 tzzM = ldf4(tzz + o + rm + x4);

        const float4 vx0 = ldf4(vx + o + gq);
        const float  vx0p = vx[o + r0 + xp4];
        const float4 vxP = ldf4(vx + o + rp + x4);
        const float4 vz0 = ldf4(vz + o + gq);
        const float  vz0m = vz[o + r0 + xm];
        const float4 vzM = ldf4(vz + o + rm + x4);

        const float txxr0[6] = {txx0m, txx0.x, txx0.y, txx0.z, txx0.w, txx0p};
        const float txzr0[6] = {txz0m, txz0.x, txz0.y, txz0.z, txz0.w, txz0p};
        const float txzrm[5] = {txzM.x, txzM.y, txzM.z, txzM.w, txzMp};
        const float tzzr0[5] = {tzz0m, tzz0.x, tzz0.y, tzz0.z, tzz0.w};
        const float tzzrp[5] = {tzzPm, tzzP.x, tzzP.y, tzzP.z, tzzP.w};

        // ---- row-z coefficients + vxnA (maps L1-hot after b=0) ----
        float a0[4], bco[4];
        float vxnA[5];
        {
            const float4 d0 = ldf4(dmp + gq);
            const float4 q0r = ldf4(rho + gq);
            const float  d0p = dmp[r0 + xp4];
            const float  q0p = rho[r0 + xp4];
            const float dd[5] = {d0.x, d0.y, d0.z, d0.w, d0p};
            const float qq[5] = {q0r.x, q0r.y, q0r.z, q0r.w, q0p};
            const float vxr0[5] = {vx0.x, vx0.y, vx0.z, vx0.w, vx0p};
            #pragma unroll
            for (int i = 0; i < 5; i++) {
                const float c   = 0.5f * DT * dd[i];
                const float inv = __fdividef(1.0f, 1.0f + c);
                const float a   = (1.0f - c) * inv;
                const float br  = __fdividef(DT * inv * INVH, qq[i]);
                if (i < 4) { a0[i] = a; bco[i] = DT * inv; }
                vxnA[i] = a * vxr0[i]
                        + br * ((txxr0[i + 1] - txxr0[i]) + (txzr0[i + 1] - txzrm[i]));
            }
        }
        // vznA: row z, x4-1..x4+3
        float vznA[5];
        {
            const float  d0m = dmp[r0 + xm];
            const float  q0m = rho[r0 + xm];
            const float4 d0 = ldf4(dmp + gq);
            const float4 q0r = ldf4(rho + gq);
            const float dd[5] = {d0m, d0.x, d0.y, d0.z, d0.w};
            const float qq[5] = {q0m, q0r.x, q0r.y, q0r.z, q0r.w};
            const float vzr0[5] = {vz0m, vz0.x, vz0.y, vz0.z, vz0.w};
            #pragma unroll
            for (int j = 0; j < 5; j++) {
                const float c   = 0.5f * DT * dd[j];
                const float inv = __fdividef(1.0f, 1.0f + c);
                const float a   = (1.0f - c) * inv;
                const float br  = __fdividef(DT * inv * INVH, qq[j]);
                vznA[j] = a * vzr0[j]
                        + br * ((txzr0[j + 1] - txzr0[j]) + (tzzrp[j] - tzzr0[j]));
            }
        }
        // vxnB: row z+1, x4..x4+3
        float vxnB[4];
        {
            const float4 dP = ldf4(dmp + rp + x4);
            const float4 qP = ldf4(rho + rp + x4);
            const float ddP[4] = {dP.x, dP.y, dP.z, dP.w};
            const float qqP[4] = {qP.x, qP.y, qP.z, qP.w};
            const float txxrp[5] = {txxPm, txxP.x, txxP.y, txxP.z, txxP.w};
            const float vxrp[4]  = {vxP.x, vxP.y, vxP.z, vxP.w};
            const float txzp_[4] = {txzP.x, txzP.y, txzP.z, txzP.w};
            #pragma unroll
            for (int i = 0; i < 4; i++) {
                const float c   = 0.5f * DT * ddP[i];
                const float inv = __fdividef(1.0f, 1.0f + c);
                const float a   = (1.0f - c) * inv;
                const float br  = __fdividef(DT * inv * INVH, qqP[i]);
                vxnB[i] = a * vxrp[i]
                        + br * ((txxrp[i + 1] - txxrp[i]) + (txzp_[i] - txzr0[i + 1]));
            }
        }
        // vznB: row z-1, x4..x4+3
        float vznB[4];
        {
            const float4 dM = ldf4(dmp + rm + x4);
            const float4 qM = ldf4(rho + rm + x4);
            const float ddM[4] = {dM.x, dM.y, dM.z, dM.w};
            const float qqM[4] = {qM.x, qM.y, qM.z, qM.w};
            const float vzrm[4]  = {vzM.x, vzM.y, vzM.z, vzM.w};
            const float tzzm_[4] = {tzzM.x, tzzM.y, tzzM.z, tzzM.w};
            const float tzz0_[4] = {tzz0.x, tzz0.y, tzz0.z, tzz0.w};
            #pragma unroll
            for (int i = 0; i < 4; i++) {
                const float c   = 0.5f * DT * ddM[i];
                const float inv = __fdividef(1.0f, 1.0f + c);
                const float a   = (1.0f - c) * inv;
                const float br  = __fdividef(DT * inv * INVH, qqM[i]);
                vznB[i] = a * vzrm[i]
                        + br * ((txzrm[i + 1] - txzrm[i]) + (tzz0_[i] - tzzm_[i]));
            }
        }

        // ---- stress material coeffs + update + writes ----
        const float txx0_[4] = {txx0.x, txx0.y, txx0.z, txx0.w};
        const float tzz0_[4] = {tzz0.x, tzz0.y, tzz0.z, tzz0.w};
        const float txz0_[4] = {txz0.x, txz0.y, txz0.z, txz0.w};
        float4 vxn4, vzn4, txxn4, tzzn4, txzn4;
        float* pvx = &vxn4.x;  float* pvz = &vzn4.x;
        float* pxx = &txxn4.x; float* pzz = &tzzn4.x; float* pxz = &txzn4.x;
        {
            const float4 s4 = ldf4(vs + gq);
            const float4 p4 = ldf4(vp + gq);
            const float4 q0r = ldf4(rho + gq);
            const float ss[4] = {s4.x, s4.y, s4.z, s4.w};
            const float pp[4] = {p4.x, p4.y, p4.z, p4.w};
            const float qq[4] = {q0r.x, q0r.y, q0r.z, q0r.w};
            #pragma unroll
            for (int i = 0; i < 4; i++) {
                const float mu   = qq[i] * ss[i] * ss[i];
                const float lam  = qq[i] * pp[i] * pp[i] - 2.0f * mu;
                const float lp2m = lam + 2.0f * mu;
                const float vx_x  = (vxnA[i + 1] - vxnA[i]) * INVH;
                const float vz_z  = (vznA[i + 1] - vznB[i]) * INVH;
                const float vx_zp = (vxnB[i] - vxnA[i]) * INVH;
                const float vz_xm = (vznA[i + 1] - vznA[i]) * INVH;
                pvx[i] = vxnA[i];
                pvz[i] = vznA[i + 1];
                pxx[i] = a0[i] * txx0_[i] + bco[i] * (lp2m * vx_x + lam * vz_z);
                pzz[i] = a0[i] * tzz0_[i] + bco[i] * (lp2m * vz_z + lam * vx_x);
                pxz[i] = a0[i] * txz0_[i] + bco[i] * (mu * (vx_zp + vz_xm));
            }
        }
        float* wbase = out + o + gq;
        __stcs(reinterpret_cast<float4*>(wbase), vxn4);
        __stcs(reinterpret_cast<float4*>(wbase + bplane), vzn4);
        __stcs(reinterpret_cast<float4*>(wbase + 2 * bplane), txxn4);
        __stcs(reinterpret_cast<float4*>(wbase + 3 * bplane), tzzn4);
        __stcs(reinterpret_cast<float4*>(wbase + 4 * bplane), txzn4);
    }
}

extern "C" void kernel_launch(void* const* d_in, const int* in_sizes, int n_in,
                              void* d_out, int out_size) {
    const float* vp  = (const float*)d_in[0];
    const float* vs  = (const float*)d_in[1];
    const float* rho = (const float*)d_in[2];
    const float* vx  = (const float*)d_in[3];
    const float* vz  = (const float*)d_in[4];
    const float* txx = (const float*)d_in[5];
    const float* tzz = (const float*)d_in[6];
    const float* txz = (const float*)d_in[7];
    const float* dmp = (const float*)d_in[8];
    float* out = (float*)d_out;

    int plane = in_sizes[0];             // NZ * NX
    int B = in_sizes[3] / plane;         // batch from vx size
    int NX = 1;
    while (NX * NX < plane) NX <<= 1;    // square power-of-two grid (2048)
    int NZ = plane / NX;

    dim3 block(32, 8);
    dim3 grid((NX / 4 + 31) / 32, (NZ + 7) / 8);
    fused_kernel<<<grid, block>>>(vp, vs, rho, vx, vz, txx, tzz, txz, dmp,
                                  out, B, NZ, NX);
}

// round 11
// speedup vs baseline: 1.1800x; 1.0360x over previous
#include <cuda_runtime.h>
#include <math.h>

#define DT   1e-3f
#define INVH 0.1f

__device__ __forceinline__ float4 ldf4(const float* p) {
    return *reinterpret_cast<const float4*>(p);
}

// Fused kernel, one batch per block, batch in the FASTEST grid dimension so
// the 4 batch-variants of a tile run in the same wave and share their
// coefficient-map reads in L2. Velocities at rows z-1/z/z+1 recomputed in
// registers from stresses (no smem, no barriers).
__global__ __launch_bounds__(256, 3)
void fused_kernel(const float* __restrict__ vp,  const float* __restrict__ vs,
                  const float* __restrict__ rho,
                  const float* __restrict__ vx,  const float* __restrict__ vz,
                  const float* __restrict__ txx, const float* __restrict__ tzz,
                  const float* __restrict__ txz, const float* __restrict__ dmp,
                  float* __restrict__ out, int B, int NZ, int NX)
{
    const int bxy = blockIdx.x;
    const int b    = bxy % 4;          // batch: fastest-varying -> L2 map sharing
    const int xblk = bxy / 4;
    const int x4 = (xblk * 32 + threadIdx.x) * 4;
    const int z  = blockIdx.y * 8 + threadIdx.y;
    if (x4 >= NX || z >= NZ) return;
    const int plane = NZ * NX;
    const int o = b * plane;

    const int r0 = z * NX;
    const int rm = ((z == 0) ? NZ - 1 : z - 1) * NX;
    const int rp = ((z == NZ - 1) ? 0 : z + 1) * NX;
    const int xm  = (x4 == 0)      ? NX - 1 : x4 - 1;
    const int xp4 = (x4 + 4 == NX) ? 0      : x4 + 4;
    const int gq = r0 + x4;

    // ---- field loads (burst for MLP) ----
    const float4 txx0 = ldf4(txx + o + gq);
    const float  txx0m = txx[o + r0 + xm];
    const float  txx0p = txx[o + r0 + xp4];
    const float4 txxP = ldf4(txx + o + rp + x4);
    const float  txxPm = txx[o + rp + xm];

    const float4 txz0 = ldf4(txz + o + gq);
    const float  txz0m = txz[o + r0 + xm];
    const float  txz0p = txz[o + r0 + xp4];
    const float4 txzM = ldf4(txz + o + rm + x4);
    const float  txzMp = txz[o + rm + xp4];
    const float4 txzP = ldf4(txz + o + rp + x4);

    const float4 tzz0 = ldf4(tzz + o + gq);
    const float  tzz0m = tzz[o + r0 + xm];
    const float4 tzzP = ldf4(tzz + o + rp + x4);
    const float  tzzPm = tzz[o + rp + xm];
    const float4 tzzM = ldf4(tzz + o + rm + x4);

    const float4 vx0 = ldf4(vx + o + gq);
    const float  vx0p = vx[o + r0 + xp4];
    const float4 vxP = ldf4(vx + o + rp + x4);
    const float4 vz0 = ldf4(vz + o + gq);
    const float  vz0m = vz[o + r0 + xm];
    const float4 vzM = ldf4(vz + o + rm + x4);

    const float txxr0[6] = {txx0m, txx0.x, txx0.y, txx0.z, txx0.w, txx0p};
    const float txzr0[6] = {txz0m, txz0.x, txz0.y, txz0.z, txz0.w, txz0p};
    const float txzrm[5] = {txzM.x, txzM.y, txzM.z, txzM.w, txzMp};
    const float tzzr0[5] = {tzz0m, tzz0.x, tzz0.y, tzz0.z, tzz0.w};
    const float tzzrp[5] = {tzzPm, tzzP.x, tzzP.y, tzzP.z, tzzP.w};

    // ---- row-z coefficients + vxnA ----
    float a0[4], bco[4];
    float vxnA[5];
    {
        const float4 d0 = ldf4(dmp + gq);
        const float4 q0r = ldf4(rho + gq);
        const float  d0p = dmp[r0 + xp4];
        const float  q0p = rho[r0 + xp4];
        const float dd[5] = {d0.x, d0.y, d0.z, d0.w, d0p};
        const float qq[5] = {q0r.x, q0r.y, q0r.z, q0r.w, q0p};
        const float vxr0[5] = {vx0.x, vx0.y, vx0.z, vx0.w, vx0p};
        #pragma unroll
        for (int i = 0; i < 5; i++) {
            const float c   = 0.5f * DT * dd[i];
            const float inv = __fdividef(1.0f, 1.0f + c);
            const float a   = (1.0f - c) * inv;
            const float br  = __fdividef(DT * inv * INVH, qq[i]);
            if (i < 4) { a0[i] = a; bco[i] = DT * inv; }
            vxnA[i] = a * vxr0[i]
                    + br * ((txxr0[i + 1] - txxr0[i]) + (txzr0[i + 1] - txzrm[i]));
        }
    }
    // vznA: row z, x4-1..x4+3
    float vznA[5];
    {
        const float  d0m = dmp[r0 + xm];
        const float  q0m = rho[r0 + xm];
        const float4 d0 = ldf4(dmp + gq);
        const float4 q0r = ldf4(rho + gq);
        const float dd[5] = {d0m, d0.x, d0.y, d0.z, d0.w};
        const float qq[5] = {q0m, q0r.x, q0r.y, q0r.z, q0r.w};
        const float vzr0[5] = {vz0m, vz0.x, vz0.y, vz0.z, vz0.w};
        #pragma unroll
        for (int j = 0; j < 5; j++) {
            const float c   = 0.5f * DT * dd[j];
            const float inv = __fdividef(1.0f, 1.0f + c);
            const float a   = (1.0f - c) * inv;
            const float br  = __fdividef(DT * inv * INVH, qq[j]);
            vznA[j] = a * vzr0[j]
                    + br * ((txzr0[j + 1] - txzr0[j]) + (tzzrp[j] - tzzr0[j]));
        }
    }
    // vxnB: row z+1, x4..x4+3
    float vxnB[4];
    {
        const float4 dP = ldf4(dmp + rp + x4);
        const float4 qP = ldf4(rho + rp + x4);
        const float ddP[4] = {dP.x, dP.y, dP.z, dP.w};
        const float qqP[4] = {qP.x, qP.y, qP.z, qP.w};
        const float txxrp[5] = {txxPm, txxP.x, txxP.y, txxP.z, txxP.w};
        const float vxrp[4]  = {vxP.x, vxP.y, vxP.z, vxP.w};
        const float txzp_[4] = {txzP.x, txzP.y, txzP.z, txzP.w};
        #pragma unroll
        for (int i = 0; i < 4; i++) {
            const float c   = 0.5f * DT * ddP[i];
            const float inv = __fdividef(1.0f, 1.0f + c);
            const float a   = (1.0f - c) * inv;
            const float br  = __fdividef(DT * inv * INVH, qqP[i]);
            vxnB[i] = a * vxrp[i]
                    + br * ((txxrp[i + 1] - txxrp[i]) + (txzp_[i] - txzr0[i + 1]));
        }
    }
    // vznB: row z-1, x4..x4+3
    float vznB[4];
    {
        const float4 dM = ldf4(dmp + rm + x4);
        const float4 qM = ldf4(rho + rm + x4);
        const float ddM[4] = {dM.x, dM.y, dM.z, dM.w};
        const float qqM[4] = {qM.x, qM.y, qM.z, qM.w};
        const float vzrm[4]  = {vzM.x, vzM.y, vzM.z, vzM.w};
        const float tzzm_[4] = {tzzM.x, tzzM.y, tzzM.z, tzzM.w};
        const float tzz0_[4] = {tzz0.x, tzz0.y, tzz0.z, tzz0.w};
        #pragma unroll
        for (int i = 0; i < 4; i++) {
            const float c   = 0.5f * DT * ddM[i];
            const float inv = __fdividef(1.0f, 1.0f + c);
            const float a   = (1.0f - c) * inv;
            const float br  = __fdividef(DT * inv * INVH, qqM[i]);
            vznB[i] = a * vzrm[i]
                    + br * ((txzrm[i + 1] - txzrm[i]) + (tzz0_[i] - tzzm_[i]));
        }
    }

    // ---- stress material coeffs + update + writes ----
    const float txx0_[4] = {txx0.x, txx0.y, txx0.z, txx0.w};
    const float tzz0_[4] = {tzz0.x, tzz0.y, tzz0.z, tzz0.w};
    const float txz0_[4] = {txz0.x, txz0.y, txz0.z, txz0.w};
    float4 vxn4, vzn4, txxn4, tzzn4, txzn4;
    float* pvx = &vxn4.x;  float* pvz = &vzn4.x;
    float* pxx = &txxn4.x; float* pzz = &tzzn4.x; float* pxz = &txzn4.x;
    {
        const float4 s4 = ldf4(vs + gq);
        const float4 p4 = ldf4(vp + gq);
        const float4 q0r = ldf4(rho + gq);
        const float ss[4] = {s4.x, s4.y, s4.z, s4.w};
        const float pp[4] = {p4.x, p4.y, p4.z, p4.w};
        const float qq[4] = {q0r.x, q0r.y, q0r.z, q0r.w};
        #pragma unroll
        for (int i = 0; i < 4; i++) {
            const float mu   = qq[i] * ss[i] * ss[i];
            const float lam  = qq[i] * pp[i] * pp[i] - 2.0f * mu;
            const float lp2m = lam + 2.0f * mu;
            const float vx_x  = (vxnA[i + 1] - vxnA[i]) * INVH;
            const float vz_z  = (vznA[i + 1] - vznB[i]) * INVH;
            const float vx_zp = (vxnB[i] - vxnA[i]) * INVH;
            const float vz_xm = (vznA[i + 1] - vznA[i]) * INVH;
            pvx[i] = vxnA[i];
            pvz[i] = vznA[i + 1];
            pxx[i] = a0[i] * txx0_[i] + bco[i] * (lp2m * vx_x + lam * vz_z);
            pzz[i] = a0[i] * tzz0_[i] + bco[i] * (lp2m * vz_z + lam * vx_x);
            pxz[i] = a0[i] * txz0_[i] + bco[i] * (mu * (vx_zp + vz_xm));
        }
    }
    const int bplane = B * plane;
    float* wbase = out + o + gq;
    __stcs(reinterpret_cast<float4*>(wbase), vxn4);
    __stcs(reinterpret_cast<float4*>(wbase + bplane), vzn4);
    __stcs(reinterpret_cast<float4*>(wbase + 2 * bplane), txxn4);
    __stcs(reinterpret_cast<float4*>(wbase + 3 * bplane), tzzn4);
    __stcs(reinterpret_cast<float4*>(wbase + 4 * bplane), txzn4);
}

extern "C" void kernel_launch(void* const* d_in, const int* in_sizes, int n_in,
                              void* d_out, int out_size) {
    const float* vp  = (const float*)d_in[0];
    const float* vs  = (const float*)d_in[1];
    const float* rho = (const float*)d_in[2];
    const float* vx  = (const float*)d_in[3];
    const float* vz  = (const float*)d_in[4];
    const float* txx = (const float*)d_in[5];
    const float* tzz = (const float*)d_in[6];
    const float* txz = (const float*)d_in[7];
    const float* dmp = (const float*)d_in[8];
    float* out = (float*)d_out;

    int plane = in_sizes[0];             // NZ * NX
    int B = in_sizes[3] / plane;         // batch from vx size (expect 4)
    int NX = 1;
    while (NX * NX < plane) NX <<= 1;    // square power-of-two grid (2048)
    int NZ = plane / NX;

    dim3 block(32, 8);
    dim3 grid(((NX / 4 + 31) / 32) * 4, (NZ + 7) / 8);   // batch folded into x (B==4)
    fused_kernel<<<grid, block>>>(vp, vs, rho, vx, vz, txx, tzz, txz, dmp,
                                  out, B, NZ, NX);
}

// round 12
// speedup vs baseline: 1.2203x; 1.0342x over previous
#include <cuda_runtime.h>
#include <math.h>

#define DT   1e-3f
#define INVH 0.1f

__device__ __forceinline__ float4 ldf4(const float* p) {
    return *reinterpret_cast<const float4*>(p);
}

// Fused kernel, one batch per block, batch fastest-varying in grid (L2 map
// sharing across the 4 batch-variants of a tile). Velocities at rows
// z-1/z/z+1 recomputed in registers from stresses. Tuned for 4 blocks/SM.
__global__ __launch_bounds__(256, 4)
void fused_kernel(const float* __restrict__ vp,  const float* __restrict__ vs,
                  const float* __restrict__ rho,
                  const float* __restrict__ vx,  const float* __restrict__ vz,
                  const float* __restrict__ txx, const float* __restrict__ tzz,
                  const float* __restrict__ txz, const float* __restrict__ dmp,
                  float* __restrict__ out, int B, int NZ, int NX)
{
    const int bxy = blockIdx.x;
    const int b    = bxy % 4;          // batch: fastest-varying -> L2 map sharing
    const int xblk = bxy / 4;
    const int x4 = (xblk * 32 + threadIdx.x) * 4;
    const int z  = blockIdx.y * 8 + threadIdx.y;
    if (x4 >= NX || z >= NZ) return;
    const int plane = NZ * NX;
    const int o = b * plane;

    const int r0 = z * NX;
    const int rm = ((z == 0) ? NZ - 1 : z - 1) * NX;
    const int rp = ((z == NZ - 1) ? 0 : z + 1) * NX;
    const int xm  = (x4 == 0)      ? NX - 1 : x4 - 1;
    const int xp4 = (x4 + 4 == NX) ? 0      : x4 + 4;
    const int gq = r0 + x4;

    // ---- stress/velocity field loads (burst for MLP) ----
    const float4 txx0 = ldf4(txx + o + gq);
    const float  txx0m = txx[o + r0 + xm];
    const float  txx0p = txx[o + r0 + xp4];
    const float4 txxP = ldf4(txx + o + rp + x4);
    const float  txxPm = txx[o + rp + xm];

    const float4 txz0 = ldf4(txz + o + gq);
    const float  txz0m = txz[o + r0 + xm];
    const float  txz0p = txz[o + r0 + xp4];
    const float4 txzM = ldf4(txz + o + rm + x4);
    const float  txzMp = txz[o + rm + xp4];
    const float4 txzP = ldf4(txz + o + rp + x4);

    const float4 tzz0 = ldf4(tzz + o + gq);
    const float  tzz0m = tzz[o + r0 + xm];
    const float4 tzzP = ldf4(tzz + o + rp + x4);
    const float  tzzPm = tzz[o + rp + xm];
    const float4 tzzM = ldf4(tzz + o + rm + x4);

    const float4 vx0 = ldf4(vx + o + gq);
    const float  vx0p = vx[o + r0 + xp4];
    const float4 vxP = ldf4(vx + o + rp + x4);
    const float4 vz0 = ldf4(vz + o + gq);
    const float  vz0m = vz[o + r0 + xm];
    const float4 vzM = ldf4(vz + o + rm + x4);

    const float txxr0[6] = {txx0m, txx0.x, txx0.y, txx0.z, txx0.w, txx0p};
    const float txzr0[6] = {txz0m, txz0.x, txz0.y, txz0.z, txz0.w, txz0p};
    const float txzrm[5] = {txzM.x, txzM.y, txzM.z, txzM.w, txzMp};
    const float tzzr0[5] = {tzz0m, tzz0.x, tzz0.y, tzz0.z, tzz0.w};
    const float tzzrp[5] = {tzzPm, tzzP.x, tzzP.y, tzzP.z, tzzP.w};

    // ---- vxnA: row z, x4..x4+4 (no persistent coeff arrays) ----
    float vxnA[5];
    {
        const float4 d0 = ldf4(dmp + gq);
        const float4 q0r = ldf4(rho + gq);
        const float  d0p = dmp[r0 + xp4];
        const float  q0p = rho[r0 + xp4];
        const float dd[5] = {d0.x, d0.y, d0.z, d0.w, d0p};
        const float qq[5] = {q0r.x, q0r.y, q0r.z, q0r.w, q0p};
        const float vxr0[5] = {vx0.x, vx0.y, vx0.z, vx0.w, vx0p};
        #pragma unroll
        for (int i = 0; i < 5; i++) {
            const float c   = 0.5f * DT * dd[i];
            const float inv = __fdividef(1.0f, 1.0f + c);
            const float a   = (1.0f - c) * inv;
            const float br  = __fdividef(DT * inv * INVH, qq[i]);
            vxnA[i] = a * vxr0[i]
                    + br * ((txxr0[i + 1] - txxr0[i]) + (txzr0[i + 1] - txzrm[i]));
        }
    }
    // ---- vznA: row z, x4-1..x4+3 ----
    float vznA[5];
    {
        const float  d0m = dmp[r0 + xm];
        const float  q0m = rho[r0 + xm];
        const float4 d0 = ldf4(dmp + gq);
        const float4 q0r = ldf4(rho + gq);
        const float dd[5] = {d0m, d0.x, d0.y, d0.z, d0.w};
        const float qq[5] = {q0m, q0r.x, q0r.y, q0r.z, q0r.w};
        const float vzr0[5] = {vz0m, vz0.x, vz0.y, vz0.z, vz0.w};
        #pragma unroll
        for (int j = 0; j < 5; j++) {
            const float c   = 0.5f * DT * dd[j];
            const float inv = __fdividef(1.0f, 1.0f + c);
            const float a   = (1.0f - c) * inv;
            const float br  = __fdividef(DT * inv * INVH, qq[j]);
            vznA[j] = a * vzr0[j]
                    + br * ((txzr0[j + 1] - txzr0[j]) + (tzzrp[j] - tzzr0[j]));
        }
    }
    // ---- vxnB: row z+1, x4..x4+3 ----
    float vxnB[4];
    {
        const float4 dP = ldf4(dmp + rp + x4);
        const float4 qP = ldf4(rho + rp + x4);
        const float ddP[4] = {dP.x, dP.y, dP.z, dP.w};
        const float qqP[4] = {qP.x, qP.y, qP.z, qP.w};
        const float txxrp[5] = {txxPm, txxP.x, txxP.y, txxP.z, txxP.w};
        const float vxrp[4]  = {vxP.x, vxP.y, vxP.z, vxP.w};
        const float txzp_[4] = {txzP.x, txzP.y, txzP.z, txzP.w};
        #pragma unroll
        for (int i = 0; i < 4; i++) {
            const float c   = 0.5f * DT * ddP[i];
            const float inv = __fdividef(1.0f, 1.0f + c);
            const float a   = (1.0f - c) * inv;
            const float br  = __fdividef(DT * inv * INVH, qqP[i]);
            vxnB[i] = a * vxrp[i]
                    + br * ((txxrp[i + 1] - txxrp[i]) + (txzp_[i] - txzr0[i + 1]));
        }
    }
    // ---- vznB: row z-1, x4..x4+3 ----
    float vznB[4];
    {
        const float4 dM = ldf4(dmp + rm + x4);
        const float4 qM = ldf4(rho + rm + x4);
        const float ddM[4] = {dM.x, dM.y, dM.z, dM.w};
        const float qqM[4] = {qM.x, qM.y, qM.z, qM.w};
        const float vzrm[4]  = {vzM.x, vzM.y, vzM.z, vzM.w};
        const float tzzm_[4] = {tzzM.x, tzzM.y, tzzM.z, tzzM.w};
        const float tzz0_[4] = {tzz0.x, tzz0.y, tzz0.z, tzz0.w};
        #pragma unroll
        for (int i = 0; i < 4; i++) {
            const float c   = 0.5f * DT * ddM[i];
            const float inv = __fdividef(1.0f, 1.0f + c);
            const float a   = (1.0f - c) * inv;
            const float br  = __fdividef(DT * inv * INVH, qqM[i]);
            vznB[i] = a * vzrm[i]
                    + br * ((txzrm[i + 1] - txzrm[i]) + (tzz0_[i] - tzzm_[i]));
        }
    }

    // ---- stress update: re-derive damping coeffs from L1-hot dmp quad ----
    const float txx0_[4] = {txx0.x, txx0.y, txx0.z, txx0.w};
    const float tzz0_[4] = {tzz0.x, tzz0.y, tzz0.z, tzz0.w};
    const float txz0_[4] = {txz0.x, txz0.y, txz0.z, txz0.w};
    float4 vxn4, vzn4, txxn4, tzzn4, txzn4;
    float* pvx = &vxn4.x;  float* pvz = &vzn4.x;
    float* pxx = &txxn4.x; float* pzz = &tzzn4.x; float* pxz = &txzn4.x;
    {
        const float4 s4 = ldf4(vs + gq);
        const float4 p4 = ldf4(vp + gq);
        const float4 q0r = ldf4(rho + gq);
        const float4 d0 = ldf4(dmp + gq);
        const float ss[4] = {s4.x, s4.y, s4.z, s4.w};
        const float pp[4] = {p4.x, p4.y, p4.z, p4.w};
        const float qq[4] = {q0r.x, q0r.y, q0r.z, q0r.w};
        const float dd[4] = {d0.x, d0.y, d0.z, d0.w};
        #pragma unroll
        for (int i = 0; i < 4; i++) {
            const float c   = 0.5f * DT * dd[i];
            const float inv = __fdividef(1.0f, 1.0f + c);
            const float a   = (1.0f - c) * inv;
            const float bco = DT * inv;
            const float mu   = qq[i] * ss[i] * ss[i];
            const float lam  = qq[i] * pp[i] * pp[i] - 2.0f * mu;
            const float lp2m = lam + 2.0f * mu;
            const float vx_x  = (vxnA[i + 1] - vxnA[i]) * INVH;
            const float vz_z  = (vznA[i + 1] - vznB[i]) * INVH;
            const float vx_zp = (vxnB[i] - vxnA[i]) * INVH;
            const float vz_xm = (vznA[i + 1] - vznA[i]) * INVH;
            pvx[i] = vxnA[i];
            pvz[i] = vznA[i + 1];
            pxx[i] = a * txx0_[i] + bco * (lp2m * vx_x + lam * vz_z);
            pzz[i] = a * tzz0_[i] + bco * (lp2m * vz_z + lam * vx_x);
            pxz[i] = a * txz0_[i] + bco * (mu * (vx_zp + vz_xm));
        }
    }
    const int bplane = B * plane;
    float* wbase = out + o + gq;
    __stcs(reinterpret_cast<float4*>(wbase), vxn4);
    __stcs(reinterpret_cast<float4*>(wbase + bplane), vzn4);
    __stcs(reinterpret_cast<float4*>(wbase + 2 * bplane), txxn4);
    __stcs(reinterpret_cast<float4*>(wbase + 3 * bplane), tzzn4);
    __stcs(reinterpret_cast<float4*>(wbase + 4 * bplane), txzn4);
}

extern "C" void kernel_launch(void* const* d_in, const int* in_sizes, int n_in,
                              void* d_out, int out_size) {
    const float* vp  = (const float*)d_in[0];
    const float* vs  = (const float*)d_in[1];
    const float* rho = (const float*)d_in[2];
    const float* vx  = (const float*)d_in[3];
    const float* vz  = (const float*)d_in[4];
    const float* txx = (const float*)d_in[5];
    const float* tzz = (const float*)d_in[6];
    const float* txz = (const float*)d_in[7];
    const float* dmp = (const float*)d_in[8];
    float* out = (float*)d_out;

    int plane = in_sizes[0];             // NZ * NX
    int B = in_sizes[3] / plane;         // batch from vx size (expect 4)
    int NX = 1;
    while (NX * NX < plane) NX <<= 1;    // square power-of-two grid (2048)
    int NZ = plane / NX;

    dim3 block(32, 8);
    dim3 grid(((NX / 4 + 31) / 32) * 4, (NZ + 7) / 8);   // batch folded into x (B==4)
    fused_kernel<<<grid, block>>>(vp, vs, rho, vx, vz, txx, tzz, txz, dmp,
                                  out, B, NZ, NX);
}

// round 13
// speedup vs baseline: 1.2425x; 1.0182x over previous
#include <cuda_runtime.h>
#include <math.h>

#define DT   1e-3f
#define INVH 0.1f

__device__ __forceinline__ float4 ldf4(const float* p) {
    return *reinterpret_cast<const float4*>(p);
}

// 1/(1+c) for c in [0, ~0.03): 4-FMA polynomial, rel err ~c^5 < 1e-7.
__device__ __forceinline__ float rcp1p(float c) {
    return fmaf(c, fmaf(c, fmaf(c, (c - 1.0f), 1.0f), -1.0f), 1.0f) * 1.0f
         ; // 1 - c + c^2 - c^3 + c^4  (Horner)
}

// Fused kernel, one batch per block, batch fastest-varying in grid (L2 map
// sharing). Velocities at rows z-1/z/z+1 recomputed in registers.
// Coefficient math: polynomial reciprocal for (1+c), single RCP for rho.
__global__ __launch_bounds__(256, 4)
void fused_kernel(const float* __restrict__ vp,  const float* __restrict__ vs,
                  const float* __restrict__ rho,
                  const float* __restrict__ vx,  const float* __restrict__ vz,
                  const float* __restrict__ txx, const float* __restrict__ tzz,
                  const float* __restrict__ txz, const float* __restrict__ dmp,
                  float* __restrict__ out, int B, int NZ, int NX)
{
    const int bxy = blockIdx.x;
    const int b    = bxy % 4;
    const int xblk = bxy / 4;
    const int x4 = (xblk * 32 + threadIdx.x) * 4;
    const int z  = blockIdx.y * 8 + threadIdx.y;
    if (x4 >= NX || z >= NZ) return;
    const int plane = NZ * NX;
    const int o = b * plane;

    const int r0 = z * NX;
    const int rm = ((z == 0) ? NZ - 1 : z - 1) * NX;
    const int rp = ((z == NZ - 1) ? 0 : z + 1) * NX;
    const int xm  = (x4 == 0)      ? NX - 1 : x4 - 1;
    const int xp4 = (x4 + 4 == NX) ? 0      : x4 + 4;
    const int gq = r0 + x4;

    // ---- stress/velocity field loads (burst for MLP) ----
    const float4 txx0 = ldf4(txx + o + gq);
    const float  txx0m = txx[o + r0 + xm];
    const float  txx0p = txx[o + r0 + xp4];
    const float4 txxP = ldf4(txx + o + rp + x4);
    const float  txxPm = txx[o + rp + xm];

    const float4 txz0 = ldf4(txz + o + gq);
    const float  txz0m = txz[o + r0 + xm];
    const float  txz0p = txz[o + r0 + xp4];
    const float4 txzM = ldf4(txz + o + rm + x4);
    const float  txzMp = txz[o + rm + xp4];
    const float4 txzP = ldf4(txz + o + rp + x4);

    const float4 tzz0 = ldf4(tzz + o + gq);
    const float  tzz0m = tzz[o + r0 + xm];
    const float4 tzzP = ldf4(tzz + o + rp + x4);
    const float  tzzPm = tzz[o + rp + xm];
    const float4 tzzM = ldf4(tzz + o + rm + x4);

    const float4 vx0 = ldf4(vx + o + gq);
    const float  vx0p = vx[o + r0 + xp4];
    const float4 vxP = ldf4(vx + o + rp + x4);
    const float4 vz0 = ldf4(vz + o + gq);
    const float  vz0m = vz[o + r0 + xm];
    const float4 vzM = ldf4(vz + o + rm + x4);

    const float txxr0[6] = {txx0m, txx0.x, txx0.y, txx0.z, txx0.w, txx0p};
    const float txzr0[6] = {txz0m, txz0.x, txz0.y, txz0.z, txz0.w, txz0p};
    const float txzrm[5] = {txzM.x, txzM.y, txzM.z, txzM.w, txzMp};
    const float tzzr0[5] = {tzz0m, tzz0.x, tzz0.y, tzz0.z, tzz0.w};
    const float tzzrp[5] = {tzzPm, tzzP.x, tzzP.y, tzzP.z, tzzP.w};

    // ---- row-z coefficients ONCE for x4-1..x4+4 (6 points) ----
    float a_z[6], br_z[6], bco_z[4];
    {
        const float4 d0 = ldf4(dmp + gq);
        const float4 q0r = ldf4(rho + gq);
        const float  d0m = dmp[r0 + xm],  d0p = dmp[r0 + xp4];
        const float  q0m = rho[r0 + xm],  q0p = rho[r0 + xp4];
        const float dd[6] = {d0m, d0.x, d0.y, d0.z, d0.w, d0p};
        const float qq[6] = {q0m, q0r.x, q0r.y, q0r.z, q0r.w, q0p};
        #pragma unroll
        for (int i = 0; i < 6; i++) {
            const float c   = 0.5f * DT * dd[i];
            const float inv = rcp1p(c);
            a_z[i]  = (1.0f - c) * inv;
            br_z[i] = __fdividef(DT * INVH * inv, qq[i]);
            if (i >= 1 && i <= 4) bco_z[i - 1] = DT * inv;
        }
    }

    // ---- vxnA: row z, x4..x4+4 (coeff index i+1) ----
    float vxnA[5];
    {
        const float vxr0[5] = {vx0.x, vx0.y, vx0.z, vx0.w, vx0p};
        #pragma unroll
        for (int i = 0; i < 5; i++)
            vxnA[i] = a_z[i + 1] * vxr0[i]
                    + br_z[i + 1] * ((txxr0[i + 1] - txxr0[i]) + (txzr0[i + 1] - txzrm[i]));
    }
    // ---- vznA: row z, x4-1..x4+3 (coeff index j) ----
    float vznA[5];
    {
        const float vzr0[5] = {vz0m, vz0.x, vz0.y, vz0.z, vz0.w};
        #pragma unroll
        for (int j = 0; j < 5; j++)
            vznA[j] = a_z[j] * vzr0[j]
                    + br_z[j] * ((txzr0[j + 1] - txzr0[j]) + (tzzrp[j] - tzzr0[j]));
    }
    // ---- vxnB: row z+1, x4..x4+3 ----
    float vxnB[4];
    {
        const float4 dP = ldf4(dmp + rp + x4);
        const float4 qP = ldf4(rho + rp + x4);
        const float ddP[4] = {dP.x, dP.y, dP.z, dP.w};
        const float qqP[4] = {qP.x, qP.y, qP.z, qP.w};
        const float txxrp[5] = {txxPm, txxP.x, txxP.y, txxP.z, txxP.w};
        const float vxrp[4]  = {vxP.x, vxP.y, vxP.z, vxP.w};
        const float txzp_[4] = {txzP.x, txzP.y, txzP.z, txzP.w};
        #pragma unroll
        for (int i = 0; i < 4; i++) {
            const float c   = 0.5f * DT * ddP[i];
            const float inv = rcp1p(c);
            const float a   = (1.0f - c) * inv;
            const float br  = __fdividef(DT * INVH * inv, qqP[i]);
            vxnB[i] = a * vxrp[i]
                    + br * ((txxrp[i + 1] - txxrp[i]) + (txzp_[i] - txzr0[i + 1]));
        }
    }
    // ---- vznB: row z-1, x4..x4+3 ----
    float vznB[4];
    {
        const float4 dM = ldf4(dmp + rm + x4);
        const float4 qM = ldf4(rho + rm + x4);
        const float ddM[4] = {dM.x, dM.y, dM.z, dM.w};
        const float qqM[4] = {qM.x, qM.y, qM.z, qM.w};
        const float vzrm[4]  = {vzM.x, vzM.y, vzM.z, vzM.w};
        const float tzzm_[4] = {tzzM.x, tzzM.y, tzzM.z, tzzM.w};
        const float tzz0_[4] = {tzz0.x, tzz0.y, tzz0.z, tzz0.w};
        #pragma unroll
        for (int i = 0; i < 4; i++) {
            const float c   = 0.5f * DT * ddM[i];
            const float inv = rcp1p(c);
            const float a   = (1.0f - c) * inv;
            const float br  = __fdividef(DT * INVH * inv, qqM[i]);
            vznB[i] = a * vzrm[i]
                    + br * ((txzrm[i + 1] - txzrm[i]) + (tzz0_[i] - tzzm_[i]));
        }
    }

    // ---- stress update (reuse row-z coeffs: a_z[i+1], bco_z[i]) ----
    const float txx0_[4] = {txx0.x, txx0.y, txx0.z, txx0.w};
    const float tzz0_[4] = {tzz0.x, tzz0.y, tzz0.z, tzz0.w};
    const float txz0_[4] = {txz0.x, txz0.y, txz0.z, txz0.w};
    float4 vxn4, vzn4, txxn4, tzzn4, txzn4;
    float* pvx = &vxn4.x;  float* pvz = &vzn4.x;
    float* pxx = &txxn4.x; float* pzz = &tzzn4.x; float* pxz = &txzn4.x;
    {
        const float4 s4 = ldf4(vs + gq);
        const float4 p4 = ldf4(vp + gq);
        const float4 q0r = ldf4(rho + gq);
        const float ss[4] = {s4.x, s4.y, s4.z, s4.w};
        const float pp[4] = {p4.x, p4.y, p4.z, p4.w};
        const float qq[4] = {q0r.x, q0r.y, q0r.z, q0r.w};
        #pragma unroll
        for (int i = 0; i < 4; i++) {
            const float a   = a_z[i + 1];
            const float bco = bco_z[i];
            const float mu   = qq[i] * ss[i] * ss[i];
            const float lam  = qq[i] * pp[i] * pp[i] - 2.0f * mu;
            const float lp2m = lam + 2.0f * mu;
            const float vx_x  = (vxnA[i + 1] - vxnA[i]) * INVH;
            const float vz_z  = (vznA[i + 1] - vznB[i]) * INVH;
            const float vx_zp = (vxnB[i] - vxnA[i]) * INVH;
            const float vz_xm = (vznA[i + 1] - vznA[i]) * INVH;
            pvx[i] = vxnA[i];
            pvz[i] = vznA[i + 1];
            pxx[i] = a * txx0_[i] + bco * (lp2m * vx_x + lam * vz_z);
            pzz[i] = a * tzz0_[i] + bco * (lp2m * vz_z + lam * vx_x);
            pxz[i] = a * txz0_[i] + bco * (mu * (vx_zp + vz_xm));
        }
    }
    const int bplane = B * plane;
    float* wbase = out + o + gq;
    __stcs(reinterpret_cast<float4*>(wbase), vxn4);
    __stcs(reinterpret_cast<float4*>(wbase + bplane), vzn4);
    __stcs(reinterpret_cast<float4*>(wbase + 2 * bplane), txxn4);
    __stcs(reinterpret_cast<float4*>(wbase + 3 * bplane), tzzn4);
    __stcs(reinterpret_cast<float4*>(wbase + 4 * bplane), txzn4);
}

extern "C" void kernel_launch(void* const* d_in, const int* in_sizes, int n_in,
                              void* d_out, int out_size) {
    const float* vp  = (const float*)d_in[0];
    const float* vs  = (const float*)d_in[1];
    const float* rho = (const float*)d_in[2];
    const float* vx  = (const float*)d_in[3];
    const float* vz  = (const float*)d_in[4];
    const float* txx = (const float*)d_in[5];
    const float* tzz = (const float*)d_in[6];
    const float* txz = (const float*)d_in[7];
    const float* dmp = (const float*)d_in[8];
    float* out = (float*)d_out;

    int plane = in_sizes[0];             // NZ * NX
    int B = in_sizes[3] / plane;         // batch from vx size (expect 4)
    int NX = 1;
    while (NX * NX < plane) NX <<= 1;    // square power-of-two grid (2048)
    int NZ = plane / NX;

    dim3 block(32, 8);
    dim3 grid(((NX / 4 + 31) / 32) * 4, (NZ + 7) / 8);   // batch folded into x (B==4)
    fused_kernel<<<grid, block>>>(vp, vs, rho, vx, vz, txx, tzz, txz, dmp,
                                  out, B, NZ, NX);
}